// round 3
// baseline (speedup 1.0000x reference)
#include <cuda_runtime.h>
#include <cstdint>

#define TT 4096
#define EE 64
#define HH 4096
#define TKK 8

// ---- scratch (device globals; no allocations allowed) ----
__device__ int   g_id[TT * TKK];    // top-8 expert ids per token (ordered desc gate)
__device__ float g_pr[TT * TKK];    // router prob for each selected expert
__device__ int   g_pos[TT * TKK];   // dispatch position within expert capacity
__device__ int   g_base[TKK * EE];  // exclusive prefix of per-(k,e) counts over k

// ============================================================================
// Kernel A: fused  [zero d_out]  ||  [logits GEMM + softmax + top-8]
//   grid = 1536 blocks x 256 thr.  bid%6==0 -> GEMM role (256 blocks,
//   16 tokens each); else zero role (1280 blocks, grid-stride float4 fill).
// GEMM: 16 tok x 64 exp tile, K-chunks of 64 staged in smem, packed f32x2 FMA,
// chunk sums accumulated in double for ranking stability.
// ============================================================================
__global__ void __launch_bounds__(256) kA(const float* __restrict__ x,
                                          const float* __restrict__ w,
                                          float* __restrict__ out,
                                          long long outn)
{
    const int bid = blockIdx.x, tid = threadIdx.x;

    if (bid % 6 != 0) {
        // -------- zero role --------
        long long zid = (long long)bid - bid / 6 - 1;       // 0..1279
        float4 z = make_float4(0.f, 0.f, 0.f, 0.f);
        float4* o4 = (float4*)out;
        long long n4 = outn >> 2;                            // outn % 4 == 0
        for (long long i = zid * 256 + tid; i < n4; i += 1280LL * 256)
            __stcs(&o4[i], z);
        return;
    }

    // -------- GEMM + top-k role --------
    const int g  = bid / 6;          // 0..255
    const int t0 = g * 16;

    __shared__ __align__(16) float Xt[64][17];  // [kk][token]
    __shared__ __align__(16) float Wt[64][68];  // [kk][expert], row stride 272B (16B mult)
    __shared__ __align__(16) float lg[16][65];  // logits tile

    const int t_idx = tid & 15;      // token within tile
    const int e4    = tid >> 4;      // expert quad 0..15

    double a0 = 0.0, a1 = 0.0, a2 = 0.0, a3 = 0.0;

    for (int h0 = 0; h0 < HH; h0 += 64) {
        #pragma unroll
        for (int r = 0; r < 4; r++) {
            int i = r * 256 + tid;
            int hh = i & 63, t = i >> 6;
            Xt[hh][t] = x[(long long)(t0 + t) * HH + h0 + hh];
        }
        #pragma unroll
        for (int r = 0; r < 16; r++) {
            int i = r * 256 + tid;
            int hh = i & 63, e = i >> 6;
            Wt[hh][e] = w[(long long)e * HH + h0 + hh];
        }
        __syncthreads();

        unsigned long long c01 = 0ull, c23 = 0ull;   // packed (0.0f,0.0f)
        #pragma unroll
        for (int kk = 0; kk < 64; kk++) {
            float xv = Xt[kk][t_idx];
            unsigned long long xx;
            asm("mov.b64 %0, {%1, %1};" : "=l"(xx) : "r"(__float_as_uint(xv)));
            ulonglong2 wv = *(const ulonglong2*)&Wt[kk][e4 * 4];
            asm("fma.rn.f32x2 %0, %1, %2, %0;" : "+l"(c01) : "l"(wv.x), "l"(xx));
            asm("fma.rn.f32x2 %0, %1, %2, %0;" : "+l"(c23) : "l"(wv.y), "l"(xx));
        }
        unsigned lo, hi;
        asm("mov.b64 {%0, %1}, %2;" : "=r"(lo), "=r"(hi) : "l"(c01));
        a0 += (double)__uint_as_float(lo);
        a1 += (double)__uint_as_float(hi);
        asm("mov.b64 {%0, %1}, %2;" : "=r"(lo), "=r"(hi) : "l"(c23));
        a2 += (double)__uint_as_float(lo);
        a3 += (double)__uint_as_float(hi);
        __syncthreads();
    }

    lg[t_idx][e4 * 4 + 0] = (float)a0;
    lg[t_idx][e4 * 4 + 1] = (float)a1;
    lg[t_idx][e4 * 4 + 2] = (float)a2;
    lg[t_idx][e4 * 4 + 3] = (float)a3;
    __syncthreads();

    // ---- softmax + iterative top-8 (one token per warp pass; 8 warps x 2) ----
    const int wrp = tid >> 5, lane = tid & 31;
    for (int tt = 0; tt < 2; tt++) {
        int t = wrp * 2 + tt;
        float v0 = lg[t][lane], v1 = lg[t][lane + 32];

        float m = fmaxf(v0, v1);
        #pragma unroll
        for (int o = 16; o; o >>= 1) m = fmaxf(m, __shfl_xor_sync(0xffffffffu, m, o));

        float z = __expf(v0 - m) + __expf(v1 - m);
        #pragma unroll
        for (int o = 16; o; o >>= 1) z += __shfl_xor_sync(0xffffffffu, z, o);

        float s0 = v0, s1 = v1;                 // selection copies (masked as we pick)
        int   wid_[TKK];
        float wex[TKK];
        float ssum = 0.f;

        #pragma unroll
        for (int k = 0; k < TKK; k++) {
            // monotone key: value desc, index asc on ties (matches lax.top_k)
            unsigned b0 = __float_as_uint(s0);
            b0 ^= (b0 & 0x80000000u) ? 0xFFFFFFFFu : 0x80000000u;
            unsigned b1 = __float_as_uint(s1);
            b1 ^= (b1 & 0x80000000u) ? 0xFFFFFFFFu : 0x80000000u;
            unsigned long long k0 = ((unsigned long long)b0 << 6) | (unsigned)(63 - lane);
            unsigned long long k1 = ((unsigned long long)b1 << 6) | (unsigned)(63 - (lane + 32));
            unsigned long long kb = (k0 > k1) ? k0 : k1;
            #pragma unroll
            for (int o = 16; o; o >>= 1) {
                unsigned long long ok = __shfl_xor_sync(0xffffffffu, kb, o);
                if (ok > kb) kb = ok;
            }
            int widx = 63 - (int)(kb & 63);
            float wv = lg[t][widx];             // broadcast read
            wid_[k] = widx;
            float ew = __expf(wv - m);
            wex[k] = ew;
            ssum += ew;
            if (widx < 32) { if (lane == widx)      s0 = __int_as_float(0xff800000); }
            else           { if (lane == widx - 32) s1 = __int_as_float(0xff800000); }
        }

        float gs    = ssum / z;                       // sum of selected gates
        float denom = fmaxf(gs, 1.1920929e-07f);      // fp32 eps clamp
        if (lane == 0) {
            int tok = t0 + t;
            #pragma unroll
            for (int k = 0; k < TKK; k++) {
                g_id[tok * TKK + k] = wid_[k];
                g_pr[tok * TKK + k] = wex[k] / (z * denom);
            }
        }
    }
}

// ============================================================================
// Kernel B0: per-(k,e) counts -> exclusive prefix over k (baseK). 1 block.
// ============================================================================
__global__ void __launch_bounds__(512) kB0()
{
    __shared__ int cnt[TKK * EE];
    int tid = threadIdx.x;
    for (int i = tid; i < TKK * EE; i += 512) cnt[i] = 0;
    __syncthreads();
    for (int i = tid; i < TT * TKK; i += 512) {
        int k = i & 7;                   // layout [t*8 + k]
        atomicAdd(&cnt[k * EE + g_id[i]], 1);
    }
    __syncthreads();
    if (tid < EE) {
        int run = 0;
        #pragma unroll
        for (int k = 0; k < TKK; k++) {
            g_base[k * EE + tid] = run;
            run += cnt[k * EE + tid];
        }
    }
}

// ============================================================================
// Kernel B1: within-slot ranks. 8 blocks (one per k).
//   hist[seg][e] over 64 segments of 64 tokens -> column-wise exclusive scan
//   over segments -> serial within-segment walk (deterministic ordering).
// ============================================================================
__global__ void __launch_bounds__(256) kB1()
{
    const int k = blockIdx.x, tid = threadIdx.x;
    __shared__ int hist[64][65];

    for (int i = tid; i < 64 * 65; i += 256) ((int*)hist)[i] = 0;
    __syncthreads();

    for (int i = tid; i < TT; i += 256)
        atomicAdd(&hist[i >> 6][g_id[i * TKK + k]], 1);
    __syncthreads();

    if (tid < 64) {                       // exclusive scan over segments per expert
        int run = 0;
        #pragma unroll
        for (int s = 0; s < 64; s++) {
            int v = hist[s][tid];
            hist[s][tid] = run;
            run += v;
        }
    }
    __syncthreads();

    if (tid < 64) {                       // serial walk within this thread's segment
        int s = tid;
        for (int j = 0; j < 64; j++) {
            int t = s * 64 + j;
            int e = g_id[t * TKK + k];
            int r = hist[s][e];
            hist[s][e] = r + 1;
            g_pos[t * TKK + k] = g_base[k * EE + e] + r;
        }
    }
}

// ============================================================================
// Kernel C: scatter nonzeros into zeroed output.
//   out = [combine_weights (T*E*C fp32) ; dispatch_mask as fp32 (T*E*C)]
// ============================================================================
__global__ void __launch_bounds__(256) kC(float* __restrict__ out, int C)
{
    int i = blockIdx.x * 256 + threadIdx.x;
    if (i >= TT * TKK) return;
    int t = i >> 3;
    int e = g_id[i];
    int p = g_pos[i];
    if (p < C) {
        long long idx = ((long long)t * EE + e) * C + p;
        out[idx] = g_pr[i];
        out[(long long)TT * EE * C + idx] = 1.0f;
    }
}

extern "C" void kernel_launch(void* const* d_in, const int* in_sizes, int n_in,
                              void* d_out, int out_size)
{
    const float* x = (const float*)d_in[0];   // hidden_states [1,4096,4096]
    const float* w = (const float*)d_in[1];   // wg_weight [64,4096]
    float* out = (float*)d_out;

    long long outn = (long long)out_size;
    int C = (int)(outn / (2LL * TT * EE));    // capacity derived from buffer size

    kA<<<1536, 256>>>(x, w, out, outn);       // zero-fill || GEMM+softmax+top8
    kB0<<<1, 512>>>();                        // counts + baseK
    kB1<<<TKK, 256>>>();                      // per-slot dispatch positions
    kC<<<(TT * TKK + 255) / 256, 256>>>(out, C);  // scatter 32768 nonzeros
}